// round 1
// baseline (speedup 1.0000x reference)
#include <cuda_runtime.h>

// out[b, q] = cos(x[b, q] + w[q]),  x: [4194304, 24] f32, w: [24] f32
// Row = 24 floats = 96 B; 4 | 24 so each float4 is within one row.
// Col base of float4 #i is ((4*i) % 24) = (i % 6) * 4.

__global__ __launch_bounds__(256)
void qfl_cos_kernel(const float4* __restrict__ x,
                    const float*  __restrict__ w,
                    float4* __restrict__ out,
                    int n4) {
    int i = blockIdx.x * blockDim.x + threadIdx.x;
    if (i >= n4) return;

    int base = (i % 6) * 4;
    float w0 = __ldg(w + base + 0);
    float w1 = __ldg(w + base + 1);
    float w2 = __ldg(w + base + 2);
    float w3 = __ldg(w + base + 3);

    float4 v = x[i];
    float4 r;
    r.x = cosf(v.x + w0);
    r.y = cosf(v.y + w1);
    r.z = cosf(v.z + w2);
    r.w = cosf(v.w + w3);
    out[i] = r;
}

extern "C" void kernel_launch(void* const* d_in, const int* in_sizes, int n_in,
                              void* d_out, int out_size) {
    const float* x = (const float*)d_in[0];
    const float* w = (const float*)d_in[1];
    float* out = (float*)d_out;

    int n = in_sizes[0];          // 100663296 elements
    int n4 = n >> 2;              // 25165824 float4s (n divisible by 4: 24*B)

    int threads = 256;
    int blocks = (n4 + threads - 1) / threads;
    qfl_cos_kernel<<<blocks, threads>>>((const float4*)x, w, (float4*)out, n4);
}

// round 2
// speedup vs baseline: 1.1161x; 1.1161x over previous
#include <cuda_runtime.h>

// out[b, q] = cos(x[b, q] + w[q]),  x: [4194304, 24] f32, w: [24] f32.
// Row = 96 B, 4 | 24 -> each float4 lies in one row; w-base = (i % 6) * 4.
// U=4 float4s per thread, block-stride, loads batched for MLP.

#define THREADS 256
#define U 4

__global__ __launch_bounds__(THREADS)
void qfl_cos_kernel(const float4* __restrict__ x,
                    const float*  __restrict__ w,
                    float4* __restrict__ out,
                    int n4) {
    int base = blockIdx.x * (THREADS * U) + threadIdx.x;

    if (base + (U - 1) * THREADS < n4) {
        // Fast path: no bounds checks. Batch all loads first (MLP=4).
        float4 v[U];
#pragma unroll
        for (int k = 0; k < U; k++)
            v[k] = __ldcs(&x[base + k * THREADS]);

#pragma unroll
        for (int k = 0; k < U; k++) {
            int i  = base + k * THREADS;
            int wb = (i % 6) * 4;
            float w0 = w[wb + 0], w1 = w[wb + 1], w2 = w[wb + 2], w3 = w[wb + 3];
            float4 r;
            r.x = cosf(v[k].x + w0);
            r.y = cosf(v[k].y + w1);
            r.z = cosf(v[k].z + w2);
            r.w = cosf(v[k].w + w3);
            __stcs(&out[i], r);
        }
    } else {
        // Tail path (unused for the bench shape, kept for safety).
#pragma unroll
        for (int k = 0; k < U; k++) {
            int i = base + k * THREADS;
            if (i < n4) {
                int wb = (i % 6) * 4;
                float4 v = __ldcs(&x[i]);
                float4 r;
                r.x = cosf(v.x + w[wb + 0]);
                r.y = cosf(v.y + w[wb + 1]);
                r.z = cosf(v.z + w[wb + 2]);
                r.w = cosf(v.w + w[wb + 3]);
                __stcs(&out[i], r);
            }
        }
    }
}

extern "C" void kernel_launch(void* const* d_in, const int* in_sizes, int n_in,
                              void* d_out, int out_size) {
    const float* x = (const float*)d_in[0];
    const float* w = (const float*)d_in[1];
    float* out = (float*)d_out;

    int n  = in_sizes[0];   // 100663296
    int n4 = n >> 2;        // 25165824 = 24576 * 1024 (exact)

    int per_block = THREADS * U;
    int blocks = (n4 + per_block - 1) / per_block;
    qfl_cos_kernel<<<blocks, THREADS>>>((const float4*)x, w, (float4*)out, n4);
}